// round 9
// baseline (speedup 1.0000x reference)
#include <cuda_runtime.h>
#include <cuda_fp16.h>
#include <cstdint>

// ---------------------------------------------------------------------------
// Fused MoE gate via 3-term fp16 split mma (m16n8k16), R7-proven accumulation:
//   x*(64w) = h0x*h0w + (h0x*h1w + h1x*h0w)   [h1x*h1w ~ 2^-22, dropped]
//   tm = 2-chain in-TC, tc = 4-chain in-TC (magnitude-balanced),
//   long-range K accumulation in fp32 FADDs. Logits = acc/64 (exact).
// X and W are pre-split into packed fp16x2 (h0,h1) planes in device scratch,
// laid out as the exact smem image consumed by cp.async.
// out (float32): [0..T*8) = topk_idx (as float), [T*8..2T*8) = weights*2.5
// ---------------------------------------------------------------------------

#define KD    4096
#define NE    256
#define BM    128
#define BK    32
#define NST   (KD / BK)           // 128 stages
#define TMAX  16384

#define PITCH_W   40              // 32 data words + 8 pad (160 B/row)
#define A_SMEM    (128 * PITCH_W * 4)           // 20480
#define B_SMEM    (256 * PITCH_W * 4)           // 40960
#define STAGE_SZ  (A_SMEM + B_SMEM)             // 61440
#define OFF_BIAS  0
#define OFF_STAGE 1024
#define SMEM_TOTAL (OFF_STAGE + 3 * STAGE_SZ)   // 185344

// Row image (32 u32 words) per (row, 32-K block):
//   word = half*16 + plane*8 + pos,  pair p at pos = (p%4)*2 + p/4
//   plane0 = h0 fp16x2 pairs, plane1 = h1 pairs; pair p covers k = p*2, p*2+1
__device__ __align__(16) uint32_t g_xsplit[(size_t)TMAX * 128 * 32]; // 256 MB
__device__ __align__(16) uint32_t g_wsplit[(size_t)128 * 256 * 32];  //   4 MB

__device__ __forceinline__ uint32_t smem_u32(const void* p) {
    uint32_t a;
    asm("{ .reg .u64 t; cvta.to.shared.u64 t, %1; cvt.u32.u64 %0, t; }"
        : "=r"(a) : "l"(p));
    return a;
}
__device__ __forceinline__ void lds_v2(uint32_t a, uint32_t& x, uint32_t& y) {
    asm volatile("ld.shared.v2.u32 {%0,%1}, [%2];" : "=r"(x), "=r"(y) : "r"(a));
}

__device__ __forceinline__ void mma_acc(float* d, const uint32_t* a,
                                        uint32_t b0, uint32_t b1) {
    asm volatile(
        "mma.sync.aligned.m16n8k16.row.col.f32.f16.f16.f32 "
        "{%0,%1,%2,%3}, {%4,%5,%6,%7}, {%8,%9}, {%0,%1,%2,%3};"
        : "+f"(d[0]), "+f"(d[1]), "+f"(d[2]), "+f"(d[3])
        : "r"(a[0]), "r"(a[1]), "r"(a[2]), "r"(a[3]), "r"(b0), "r"(b1));
}
__device__ __forceinline__ void mma_zro(float* d, const uint32_t* a,
                                        uint32_t b0, uint32_t b1) {
    asm volatile(
        "mma.sync.aligned.m16n8k16.row.col.f32.f16.f16.f32 "
        "{%0,%1,%2,%3}, {%4,%5,%6,%7}, {%8,%9}, {%10,%11,%12,%13};"
        : "=f"(d[0]), "=f"(d[1]), "=f"(d[2]), "=f"(d[3])
        : "r"(a[0]), "r"(a[1]), "r"(a[2]), "r"(a[3]), "r"(b0), "r"(b1),
          "f"(0.0f), "f"(0.0f), "f"(0.0f), "f"(0.0f));
}

// -------------------- pre-split kernels (exact smem image) -----------------
__device__ __forceinline__ uint32_t split_word(const float* src, size_t base,
                                               int k, int plane) {
    float x0 = src[base + k], x1 = src[base + k + 1];
    __half2 h0 = __floats2half2_rn(x0, x1);
    if (plane == 0) return *reinterpret_cast<uint32_t*>(&h0);
    float r0 = x0 - __half2float(__low2half(h0));
    float r1 = x1 - __half2float(__high2half(h0));
    __half2 h1 = __floats2half2_rn(r0, r1);
    return *reinterpret_cast<uint32_t*>(&h1);
}

__global__ __launch_bounds__(256)
void xsplit_kernel(const float* __restrict__ X, int T) {
    size_t id = (size_t)blockIdx.x * 256 + threadIdx.x;   // one u32 out
    int w   = (int)(id & 31);
    size_t rkb = id >> 5;
    int kb  = (int)(rkb & 127);
    size_t m = rkb >> 7;
    if (m >= (size_t)T) return;
    int half = w >> 4, plane = (w >> 3) & 1, pos = w & 7;
    int p = ((pos & 1) << 2) | (pos >> 1);
    int k = kb * BK + half * 16 + p * 2;
    g_xsplit[id] = split_word(X, m * KD, k, plane);
}

__global__ __launch_bounds__(256)
void wsplit_kernel(const float* __restrict__ W) {
    size_t id = (size_t)blockIdx.x * 256 + threadIdx.x;   // 128*256*32 total
    int w  = (int)(id & 31);
    size_t rn = id >> 5;
    int n  = (int)(rn & 255);
    int kb = (int)(rn >> 8);
    int half = w >> 4, plane = (w >> 3) & 1, pos = w & 7;
    int p = ((pos & 1) << 2) | (pos >> 1);
    int k = kb * BK + half * 16 + p * 2;
    // scale by 64 so h1 stays normal-range; epilogue divides by 64 (exact)
    float x0 = W[(size_t)n * KD + k] * 64.0f;
    float x1 = W[(size_t)n * KD + k + 1] * 64.0f;
    __half2 h0 = __floats2half2_rn(x0, x1);
    uint32_t v;
    if (plane == 0) v = *reinterpret_cast<uint32_t*>(&h0);
    else {
        float r0 = x0 - __half2float(__low2half(h0));
        float r1 = x1 - __half2float(__high2half(h0));
        __half2 h1 = __floats2half2_rn(r0, r1);
        v = *reinterpret_cast<uint32_t*>(&h1);
    }
    g_wsplit[id] = v;
}

// ------------------------------- main kernel -------------------------------
__global__ __launch_bounds__(512, 1)
void moe_kernel(const float* __restrict__ bias, float* __restrict__ out, int T)
{
    extern __shared__ char sm[];
    const uint32_t sb = smem_u32(sm);
    const int tid = threadIdx.x, wid = tid >> 5, lane = tid & 31;
    const int wm = wid & 3, wn = wid >> 2;           // 4x4 warp grid
    const int m0 = blockIdx.x * BM;
    const int fr = lane >> 2, fc = lane & 3;

    if (tid < NE) ((float*)(sm + OFF_BIAS))[tid] = bias[tid];

#define ISSUE(s) do {                                                          \
    uint32_t stb_ = sb + OFF_STAGE + ((s) % 3) * STAGE_SZ;                     \
    _Pragma("unroll")                                                          \
    for (int i_ = 0; i_ < 2; i_++) {       /* A: 128 rows x 128B */            \
        int id_ = tid + i_ * 512;                                              \
        int r_ = id_ >> 3, c_ = id_ & 7;                                       \
        const uint32_t* src_ = g_xsplit                                        \
            + ((size_t)(m0 + r_) * 128 + (s)) * 32 + c_ * 4;                   \
        asm volatile("cp.async.cg.shared.global [%0], [%1], 16;"               \
            :: "r"(stb_ + r_ * (PITCH_W * 4) + c_ * 16), "l"(src_));           \
    }                                                                          \
    _Pragma("unroll")                                                          \
    for (int i_ = 0; i_ < 4; i_++) {       /* B: 256 rows x 128B */            \
        int id_ = tid + i_ * 512;                                              \
        int n_ = id_ >> 3, c_ = id_ & 7;                                       \
        const uint32_t* src_ = g_wsplit                                        \
            + ((size_t)(s) * 256 + n_) * 32 + c_ * 4;                          \
        asm volatile("cp.async.cg.shared.global [%0], [%1], 16;"               \
            :: "r"(stb_ + A_SMEM + n_ * (PITCH_W * 4) + c_ * 16), "l"(src_));  \
    }                                                                          \
} while (0)

    ISSUE(0); asm volatile("cp.async.commit_group;" ::: "memory");
    ISSUE(1); asm volatile("cp.async.commit_group;" ::: "memory");

    float acc[2][8][4];
#pragma unroll
    for (int i = 0; i < 2; i++)
#pragma unroll
        for (int j = 0; j < 8; j++)
#pragma unroll
            for (int q = 0; q < 4; q++) acc[i][j][q] = 0.0f;

    for (int s = 0; s < NST; s++) {
        asm volatile("cp.async.wait_group 1;" ::: "memory");
        __syncthreads();
        if (s + 2 < NST) ISSUE(s + 2);
        asm volatile("cp.async.commit_group;" ::: "memory");

        const uint32_t stb = sb + OFF_STAGE + (s % 3) * STAGE_SZ;

        // ---- A fragments: AH/AL[mt][ks] = {a0,a1,a2,a3} (fp16x2 regs) ----
        uint32_t AH[2][2][4], AL[2][2][4];
#pragma unroll
        for (int mt = 0; mt < 2; mt++) {
            const int r0 = (wm * 2 + mt) * 16 + fr;
#pragma unroll
            for (int ks = 0; ks < 2; ks++) {
                uint32_t base = stb + (uint32_t)(r0 * PITCH_W + ks * 16 + fc * 2) * 4;
                lds_v2(base,              AH[mt][ks][0], AH[mt][ks][2]);
                lds_v2(base + 8 * PITCH_W * 4, AH[mt][ks][1], AH[mt][ks][3]);
                lds_v2(base + 32,         AL[mt][ks][0], AL[mt][ks][2]);
                lds_v2(base + 8 * PITCH_W * 4 + 32, AL[mt][ks][1], AL[mt][ks][3]);
            }
        }

        // ---- N tiles ----
#pragma unroll
        for (int nt = 0; nt < 8; nt++) {
            const int n = (wn * 8 + nt) * 8 + fr;
            uint32_t bbase = stb + A_SMEM + (uint32_t)(n * PITCH_W + fc * 2) * 4;
            uint32_t BH[2][2], BL[2][2];
            lds_v2(bbase,      BH[0][0], BH[0][1]);   // ks0 h0 (b0,b1)
            lds_v2(bbase + 32, BL[0][0], BL[0][1]);   // ks0 h1
            lds_v2(bbase + 64, BH[1][0], BH[1][1]);   // ks1 h0
            lds_v2(bbase + 96, BL[1][0], BL[1][1]);   // ks1 h1
#pragma unroll
            for (int mt = 0; mt < 2; mt++) {
                float tm[4], tc[4];
                mma_zro(tm, AH[mt][0], BH[0][0], BH[0][1]);  // h0*h0 ks0
                mma_acc(tm, AH[mt][1], BH[1][0], BH[1][1]);  // h0*h0 ks1
                mma_zro(tc, AH[mt][0], BL[0][0], BL[0][1]);  // h0*h1 ks0
                mma_acc(tc, AL[mt][0], BH[0][0], BH[0][1]);  // h1*h0 ks0
                mma_acc(tc, AH[mt][1], BL[1][0], BL[1][1]);  // h0*h1 ks1
                mma_acc(tc, AL[mt][1], BH[1][0], BH[1][1]);  // h1*h0 ks1
                acc[mt][nt][0] += tm[0] + tc[0];
                acc[mt][nt][1] += tm[1] + tc[1];
                acc[mt][nt][2] += tm[2] + tc[2];
                acc[mt][nt][3] += tm[3] + tc[3];
            }
        }
    }
#undef ISSUE

    __syncthreads();   // all warps done with stage buffers

    // ---------------- dump logits (unscale by 1/64) to smem ---------------
    {
        float* sc = (float*)(sm + OFF_STAGE);
        const float inv = 1.0f / 64.0f;
#pragma unroll
        for (int mt = 0; mt < 2; mt++) {
            int r = wm * 32 + mt * 16 + fr;
#pragma unroll
            for (int nt = 0; nt < 8; nt++) {
                int c = wn * 64 + nt * 8 + fc * 2;
                sc[r * 257 + c]           = acc[mt][nt][0] * inv;
                sc[r * 257 + c + 1]       = acc[mt][nt][1] * inv;
                sc[(r + 8) * 257 + c]     = acc[mt][nt][2] * inv;
                sc[(r + 8) * 257 + c + 1] = acc[mt][nt][3] * inv;
            }
        }
    }
    __syncthreads();

    // ---------------- fused gating (warps 0-3, one token per thread) ------
    if (wid < 4) {
        const int row = wid * 32 + lane;
        float* srow = (float*)(sm + OFF_STAGE) + row * 257;
        const float* bs = (const float*)(sm + OFF_BIAS);

        float gs[8];
#pragma unroll
        for (int g = 0; g < 8; g++) {
            float m1 = -1e30f, m2 = -1e30f;
#pragma unroll
            for (int i = 0; i < 32; i++) {
                float lg = srow[g * 32 + i];
                float scv = 1.0f / (1.0f + expf(-lg));   // sigmoid
                float v = scv + bs[g * 32 + i];          // scores_for_choice
                srow[g * 32 + i] = v;
                if (v > m1) { m2 = m1; m1 = v; }
                else if (v > m2) m2 = v;
            }
            gs[g] = m1 + m2;
        }
        // stable top-4 groups (ties -> lower index)
        int mask = 0;
#pragma unroll
        for (int j = 0; j < 8; j++) {
            int rk = 0;
#pragma unroll
            for (int j2 = 0; j2 < 8; j2++)
                rk += (gs[j2] > gs[j]) || (gs[j2] == gs[j] && j2 < j);
            if (rk < 4) mask |= 1 << j;
        }
        // stable top-8 experts over masked scores (matches lax.top_k ties)
        float bv[8]; int bi[8];
#pragma unroll
        for (int k = 0; k < 8; k++) { bv[k] = -1e30f; bi[k] = 0; }
        for (int e = 0; e < NE; e++) {
            float v = ((mask >> (e >> 5)) & 1) ? srow[e] : 0.0f;
            if (v > bv[7]) {
                bv[7] = v; bi[7] = e;
#pragma unroll
                for (int k = 7; k > 0; k--)
                    if (bv[k] > bv[k - 1]) {
                        float tv = bv[k]; bv[k] = bv[k - 1]; bv[k - 1] = tv;
                        int ti = bi[k];  bi[k] = bi[k - 1]; bi[k - 1] = ti;
                    }
            }
        }
        float ws = 0.0f, wv[8];
#pragma unroll
        for (int k = 0; k < 8; k++) { wv[k] = bv[k] - bs[bi[k]]; ws += wv[k]; }
        const size_t token = (size_t)(m0 + row);
#pragma unroll
        for (int k = 0; k < 8; k++) {
            out[token * 8 + k] = (float)bi[k];
            out[(size_t)T * 8 + token * 8 + k] = wv[k] / (ws + 1e-20f) * 2.5f;
        }
    }
}

extern "C" void kernel_launch(void* const* d_in, const int* in_sizes, int n_in,
                              void* d_out, int out_size)
{
    const float* X    = (const float*)d_in[0];
    const float* W    = (const float*)d_in[1];
    const float* bias = (const float*)d_in[2];
    float* out = (float*)d_out;

    const int T = in_sizes[0] / KD;   // 16384

    xsplit_kernel<<<(int)(((size_t)T * 128 * 32) / 256), 256>>>(X, T);
    wsplit_kernel<<<(128 * 256 * 32) / 256, 256>>>(W);

    cudaFuncSetAttribute(moe_kernel,
                         cudaFuncAttributeMaxDynamicSharedMemorySize, SMEM_TOTAL);
    moe_kernel<<<T / BM, 512, SMEM_TOTAL>>>(bias, out, T);
}

// round 10
// speedup vs baseline: 1.6291x; 1.6291x over previous
#include <cuda_runtime.h>
#include <cuda_fp16.h>
#include <cstdint>

// ---------------------------------------------------------------------------
// Fused MoE gate via 3-term fp16 split mma (m16n8k16), R7/R9-proven numerics:
//   x*(64w) = h0x*h0w + h0x*h1w + h1x*h0w   [h1x*h1w ~ 2^-22, dropped]
// Per K32: tm = 2-chain (main), tc0/tc1 = independent 2-chains (corrections),
// long-range K accumulation in fp32 FADDs. K64 stages, 2-deep cp.async pipe.
// X and W pre-split into packed fp16x2 (h0,h1) smem-image planes.
// out (float32): [0..T*8) = topk_idx (as float), [T*8..2T*8) = weights*2.5
// ---------------------------------------------------------------------------

#define KD    4096
#define NE    256
#define BM    128
#define NST   64                  // K64 stages
#define TMAX  16384

#define PITCH_W   72              // 64 data words + 8 pad (288 B/row)
#define A_SMEM    (128 * PITCH_W * 4)           // 36864
#define B_SMEM    (256 * PITCH_W * 4)           // 73728
#define STAGE_SZ  (A_SMEM + B_SMEM)             // 110592
#define OFF_BIAS  0
#define OFF_STAGE 1024
#define SMEM_TOTAL (OFF_STAGE + 2 * STAGE_SZ)   // 222208

// Row image (32 u32 words) per (row, K32-block):
//   word = ks*16 + plane*8 + pos,  pair p at pos: p = ((pos&1)<<2)|(pos>>1)
__device__ __align__(16) uint32_t g_xsplit[(size_t)TMAX * 128 * 32]; // 256 MB
__device__ __align__(16) uint32_t g_wsplit[(size_t)128 * 256 * 32];  //   4 MB

__device__ __forceinline__ uint32_t smem_u32(const void* p) {
    uint32_t a;
    asm("{ .reg .u64 t; cvta.to.shared.u64 t, %1; cvt.u32.u64 %0, t; }"
        : "=r"(a) : "l"(p));
    return a;
}
__device__ __forceinline__ void lds_v2(uint32_t a, uint32_t& x, uint32_t& y) {
    asm volatile("ld.shared.v2.u32 {%0,%1}, [%2];" : "=r"(x), "=r"(y) : "r"(a));
}
__device__ __forceinline__ void mma_acc(float* d, const uint32_t* a,
                                        uint32_t b0, uint32_t b1) {
    asm volatile(
        "mma.sync.aligned.m16n8k16.row.col.f32.f16.f16.f32 "
        "{%0,%1,%2,%3}, {%4,%5,%6,%7}, {%8,%9}, {%0,%1,%2,%3};"
        : "+f"(d[0]), "+f"(d[1]), "+f"(d[2]), "+f"(d[3])
        : "r"(a[0]), "r"(a[1]), "r"(a[2]), "r"(a[3]), "r"(b0), "r"(b1));
}
__device__ __forceinline__ void mma_zro(float* d, const uint32_t* a,
                                        uint32_t b0, uint32_t b1) {
    asm volatile(
        "mma.sync.aligned.m16n8k16.row.col.f32.f16.f16.f32 "
        "{%0,%1,%2,%3}, {%4,%5,%6,%7}, {%8,%9}, {%10,%11,%12,%13};"
        : "=f"(d[0]), "=f"(d[1]), "=f"(d[2]), "=f"(d[3])
        : "r"(a[0]), "r"(a[1]), "r"(a[2]), "r"(a[3]), "r"(b0), "r"(b1),
          "f"(0.0f), "f"(0.0f), "f"(0.0f), "f"(0.0f));
}

// ---------------- vectorized X pre-split: 64B in, 64B out per thread -------
__global__ __launch_bounds__(256)
void xsplit_kernel(const float* __restrict__ X, int T) {
    size_t id = (size_t)blockIdx.x * 256 + threadIdx.x;
    int half = (int)(id & 1);
    int kb   = (int)((id >> 1) & 127);
    size_t m = id >> 8;
    if (m >= (size_t)T) return;

    const float4* src = (const float4*)(X + m * KD + kb * 32 + half * 16);
    float4 f0 = src[0], f1 = src[1], f2 = src[2], f3 = src[3];
    float x[16] = {f0.x,f0.y,f0.z,f0.w, f1.x,f1.y,f1.z,f1.w,
                   f2.x,f2.y,f2.z,f2.w, f3.x,f3.y,f3.z,f3.w};
    uint32_t p0[8], p1[8];
#pragma unroll
    for (int p = 0; p < 8; p++) {
        float a = x[2*p], b = x[2*p+1];
        __half2 h0 = __floats2half2_rn(a, b);
        p0[p] = *reinterpret_cast<uint32_t*>(&h0);
        float r0 = a - __half2float(__low2half(h0));
        float r1 = b - __half2float(__high2half(h0));
        __half2 h1 = __floats2half2_rn(r0, r1);
        p1[p] = *reinterpret_cast<uint32_t*>(&h1);
    }
    uint4* dst = (uint4*)(g_xsplit + ((m * 128 + kb) * 32) + half * 16);
    dst[0] = make_uint4(p0[0], p0[4], p0[1], p0[5]);   // words 0-3
    dst[1] = make_uint4(p0[2], p0[6], p0[3], p0[7]);   // words 4-7
    dst[2] = make_uint4(p1[0], p1[4], p1[1], p1[5]);   // words 8-11
    dst[3] = make_uint4(p1[2], p1[6], p1[3], p1[7]);   // words 12-15
}

// ---------------- W pre-split (scaled by 64; unscaled in epilogue) ---------
__global__ __launch_bounds__(256)
void wsplit_kernel(const float* __restrict__ W) {
    size_t id = (size_t)blockIdx.x * 256 + threadIdx.x;   // 128*256*32 total
    int w  = (int)(id & 31);
    size_t rn = id >> 5;
    int n  = (int)(rn & 255);
    int kb = (int)(rn >> 8);
    int half = w >> 4, plane = (w >> 3) & 1, pos = w & 7;
    int p = ((pos & 1) << 2) | (pos >> 1);
    int k = kb * 32 + half * 16 + p * 2;
    float x0 = W[(size_t)n * KD + k] * 64.0f;
    float x1 = W[(size_t)n * KD + k + 1] * 64.0f;
    __half2 h0 = __floats2half2_rn(x0, x1);
    uint32_t v;
    if (plane == 0) v = *reinterpret_cast<uint32_t*>(&h0);
    else {
        float r0 = x0 - __half2float(__low2half(h0));
        float r1 = x1 - __half2float(__high2half(h0));
        __half2 h1 = __floats2half2_rn(r0, r1);
        v = *reinterpret_cast<uint32_t*>(&h1);
    }
    g_wsplit[id] = v;
}

// ------------------------------- main kernel -------------------------------
__global__ __launch_bounds__(512, 1)
void moe_kernel(const float* __restrict__ bias, float* __restrict__ out, int T)
{
    extern __shared__ char sm[];
    const uint32_t sb = smem_u32(sm);
    const int tid = threadIdx.x, wid = tid >> 5, lane = tid & 31;
    const int wm = wid & 3, wn = wid >> 2;           // 4x4 warp grid
    const int m0 = blockIdx.x * BM;
    const int fr = lane >> 2, fc = lane & 3;

    if (tid < NE) ((float*)(sm + OFF_BIAS))[tid] = bias[tid];

#define ISSUE(s) do {                                                          \
    uint32_t stb_ = sb + OFF_STAGE + ((s) & 1) * STAGE_SZ;                     \
    _Pragma("unroll")                                                          \
    for (int i_ = 0; i_ < 4; i_++) {       /* A: 128 rows x 256B */            \
        int id_ = tid + i_ * 512;                                              \
        int r_ = id_ >> 4, c_ = id_ & 15;                                      \
        const uint32_t* src_ = g_xsplit                                        \
            + ((size_t)(m0 + r_) * 128 + (s) * 2 + (c_ >> 3)) * 32             \
            + (c_ & 7) * 4;                                                    \
        asm volatile("cp.async.cg.shared.global [%0], [%1], 16;"               \
            :: "r"(stb_ + r_ * (PITCH_W * 4) + c_ * 16), "l"(src_));           \
    }                                                                          \
    _Pragma("unroll")                                                          \
    for (int i_ = 0; i_ < 8; i_++) {       /* B: 256 rows x 256B */            \
        int id_ = tid + i_ * 512;                                              \
        int n_ = id_ >> 4, c_ = id_ & 15;                                      \
        const uint32_t* src_ = g_wsplit                                        \
            + (((size_t)(s) * 2 + (c_ >> 3)) * 256 + n_) * 32 + (c_ & 7) * 4;  \
        asm volatile("cp.async.cg.shared.global [%0], [%1], 16;"               \
            :: "r"(stb_ + A_SMEM + n_ * (PITCH_W * 4) + c_ * 16), "l"(src_));  \
    }                                                                          \
} while (0)

    ISSUE(0); asm volatile("cp.async.commit_group;" ::: "memory");
    ISSUE(1); asm volatile("cp.async.commit_group;" ::: "memory");

    float acc[2][8][4];
#pragma unroll
    for (int i = 0; i < 2; i++)
#pragma unroll
        for (int j = 0; j < 8; j++)
#pragma unroll
            for (int q = 0; q < 4; q++) acc[i][j][q] = 0.0f;

    for (int s = 0; s < NST; s++) {
        asm volatile("cp.async.wait_group 1;" ::: "memory");
        __syncthreads();
        const uint32_t stb = sb + OFF_STAGE + (s & 1) * STAGE_SZ;

#pragma unroll
        for (int blk = 0; blk < 2; blk++) {          // two K32 halves
            uint32_t AH[2][2][4], AL[2][2][4];       // [mt][ks][frag]
#pragma unroll
            for (int mt = 0; mt < 2; mt++) {
                const int r0 = (wm * 2 + mt) * 16 + fr;
#pragma unroll
                for (int ks = 0; ks < 2; ks++) {
                    uint32_t base = stb + (uint32_t)r0 * (PITCH_W * 4)
                                  + blk * 128 + ks * 64 + fc * 8;
                    lds_v2(base,        AH[mt][ks][0], AH[mt][ks][2]);
                    lds_v2(base + 2304, AH[mt][ks][1], AH[mt][ks][3]);
                    lds_v2(base + 32,   AL[mt][ks][0], AL[mt][ks][2]);
                    lds_v2(base + 2336, AL[mt][ks][1], AL[mt][ks][3]);
                }
            }
#pragma unroll
            for (int nt = 0; nt < 8; nt++) {
                const int n = (wn * 8 + nt) * 8 + fr;
                uint32_t bbase = stb + A_SMEM + (uint32_t)n * (PITCH_W * 4)
                               + blk * 128 + fc * 8;
                uint32_t BH[2][2], BL[2][2];
                lds_v2(bbase,      BH[0][0], BH[0][1]);   // ks0 h0
                lds_v2(bbase + 32, BL[0][0], BL[0][1]);   // ks0 h1
                lds_v2(bbase + 64, BH[1][0], BH[1][1]);   // ks1 h0
                lds_v2(bbase + 96, BL[1][0], BL[1][1]);   // ks1 h1
#pragma unroll
                for (int mt = 0; mt < 2; mt++) {
                    float tm[4], tc0[4], tc1[4];
                    mma_zro(tm,  AH[mt][0], BH[0][0], BH[0][1]);  // h0*h0 ks0
                    mma_acc(tm,  AH[mt][1], BH[1][0], BH[1][1]);  // h0*h0 ks1
                    mma_zro(tc0, AH[mt][0], BL[0][0], BL[0][1]);  // h0*h1 ks0
                    mma_acc(tc0, AL[mt][0], BH[0][0], BH[0][1]);  // h1*h0 ks0
                    mma_zro(tc1, AH[mt][1], BL[1][0], BL[1][1]);  // h0*h1 ks1
                    mma_acc(tc1, AL[mt][1], BH[1][0], BH[1][1]);  // h1*h0 ks1
#pragma unroll
                    for (int q = 0; q < 4; q++)
                        acc[mt][nt][q] += tm[q] + tc0[q] + tc1[q];
                }
            }
        }

        __syncthreads();
        if (s + 2 < NST) ISSUE(s + 2);
        asm volatile("cp.async.commit_group;" ::: "memory");
    }
#undef ISSUE

    // ---------------- dump logits (unscale by 1/64) to smem ---------------
    {
        float* sc = (float*)(sm + OFF_STAGE);
        const float inv = 1.0f / 64.0f;
#pragma unroll
        for (int mt = 0; mt < 2; mt++) {
            int r = wm * 32 + mt * 16 + fr;
#pragma unroll
            for (int nt = 0; nt < 8; nt++) {
                int c = wn * 64 + nt * 8 + fc * 2;
                sc[r * 257 + c]           = acc[mt][nt][0] * inv;
                sc[r * 257 + c + 1]       = acc[mt][nt][1] * inv;
                sc[(r + 8) * 257 + c]     = acc[mt][nt][2] * inv;
                sc[(r + 8) * 257 + c + 1] = acc[mt][nt][3] * inv;
            }
        }
    }
    __syncthreads();

    // ---------------- fused gating (warps 0-3, one token per thread) ------
    if (wid < 4) {
        const int row = wid * 32 + lane;
        float* srow = (float*)(sm + OFF_STAGE) + row * 257;
        const float* bs = (const float*)(sm + OFF_BIAS);

        float gs[8];
#pragma unroll
        for (int g = 0; g < 8; g++) {
            float m1 = -1e30f, m2 = -1e30f;
#pragma unroll
            for (int i = 0; i < 32; i++) {
                float lg = srow[g * 32 + i];
                float scv = 1.0f / (1.0f + expf(-lg));   // sigmoid
                float v = scv + bs[g * 32 + i];          // scores_for_choice
                srow[g * 32 + i] = v;
                if (v > m1) { m2 = m1; m1 = v; }
                else if (v > m2) m2 = v;
            }
            gs[g] = m1 + m2;
        }
        int mask = 0;
#pragma unroll
        for (int j = 0; j < 8; j++) {
            int rk = 0;
#pragma unroll
            for (int j2 = 0; j2 < 8; j2++)
                rk += (gs[j2] > gs[j]) || (gs[j2] == gs[j] && j2 < j);
            if (rk < 4) mask |= 1 << j;
        }
        float bv[8]; int bi[8];
#pragma unroll
        for (int k = 0; k < 8; k++) { bv[k] = -1e30f; bi[k] = 0; }
        for (int e = 0; e < NE; e++) {
            float v = ((mask >> (e >> 5)) & 1) ? srow[e] : 0.0f;
            if (v > bv[7]) {
                bv[7] = v; bi[7] = e;
#pragma unroll
                for (int k = 7; k > 0; k--)
                    if (bv[k] > bv[k - 1]) {
                        float tv = bv[k]; bv[k] = bv[k - 1]; bv[k - 1] = tv;
                        int ti = bi[k];  bi[k] = bi[k - 1]; bi[k - 1] = ti;
                    }
            }
        }
        float ws = 0.0f, wv[8];
#pragma unroll
        for (int k = 0; k < 8; k++) { wv[k] = bv[k] - bs[bi[k]]; ws += wv[k]; }
        const size_t token = (size_t)(m0 + row);
#pragma unroll
        for (int k = 0; k < 8; k++) {
            out[token * 8 + k] = (float)bi[k];
            out[(size_t)T * 8 + token * 8 + k] = wv[k] / (ws + 1e-20f) * 2.5f;
        }
    }
}

extern "C" void kernel_launch(void* const* d_in, const int* in_sizes, int n_in,
                              void* d_out, int out_size)
{
    const float* X    = (const float*)d_in[0];
    const float* W    = (const float*)d_in[1];
    const float* bias = (const float*)d_in[2];
    float* out = (float*)d_out;

    const int T = in_sizes[0] / KD;   // 16384

    xsplit_kernel<<<T, 256>>>(X, T);                      // T*256 threads
    wsplit_kernel<<<(128 * 256 * 32) / 256, 256>>>(W);

    cudaFuncSetAttribute(moe_kernel,
                         cudaFuncAttributeMaxDynamicSharedMemorySize, SMEM_TOTAL);
    moe_kernel<<<T / BM, 512, SMEM_TOTAL>>>(bias, out, T);
}